// round 1
// baseline (speedup 1.0000x reference)
#include <cuda_runtime.h>

// Problem constants (fixed by the reference)
#define BB 2
#define LL 2048
#define DD 1024
#define HH 16
#define DKH 64
#define MTOT (BB*LL)   // 4096

// Scratch (no cudaMalloc allowed) — (B*H, L, DK) layouts for q,k,v; (B,L,D) for o
__device__ float g_q[BB*HH*LL*DKH];
__device__ float g_k[BB*HH*LL*DKH];
__device__ float g_v[BB*HH*LL*DKH];
__device__ float g_o[BB*LL*DD];

// ----------------------------------------------------------------------------
// GEMM: C[m,n] = sum_k A[m,k] * W[n,k] + bias[n]
// A: MxK row-major, W: NxK row-major (nn.Linear weight, y = x @ W^T + b)
// MODE 0: write C row-major MxN
// MODE 1: scatter to (B,H,L,DK): m=(b,l), n=(h,dk)
// Tiles: BM=BN=64, BK=16, 256 threads, 4x4 per thread.
// ----------------------------------------------------------------------------
template<int MODE>
__global__ void gemm64(const float* __restrict__ A, const float* __restrict__ W,
                       const float* __restrict__ bias, float* __restrict__ C,
                       int M, int N, int K) {
    __shared__ float sA[16][64];   // [k][m] transposed
    __shared__ float sB[16][64];   // [k][n] transposed

    const int tid = threadIdx.x;
    const int ty  = tid >> 4;      // 0..15
    const int tx  = tid & 15;      // 0..15
    const int mBase = blockIdx.x * 64;
    const int nBase = blockIdx.y * 64;

    const int lr = tid >> 2;          // 0..63 row within tile
    const int lk = (tid & 3) * 4;     // 0,4,8,12

    const float* Ap = A + (size_t)(mBase + lr) * K + lk;
    const float* Wp = W + (size_t)(nBase + lr) * K + lk;

    float acc[4][4] = {};

    for (int k0 = 0; k0 < K; k0 += 16) {
        float4 av = *(const float4*)(Ap + k0);
        float4 wv = *(const float4*)(Wp + k0);
        sA[lk + 0][lr] = av.x; sA[lk + 1][lr] = av.y;
        sA[lk + 2][lr] = av.z; sA[lk + 3][lr] = av.w;
        sB[lk + 0][lr] = wv.x; sB[lk + 1][lr] = wv.y;
        sB[lk + 2][lr] = wv.z; sB[lk + 3][lr] = wv.w;
        __syncthreads();

        #pragma unroll
        for (int k = 0; k < 16; k++) {
            float4 a = *(const float4*)&sA[k][ty * 4];
            float4 b = *(const float4*)&sB[k][tx * 4];
            acc[0][0] += a.x * b.x; acc[0][1] += a.x * b.y; acc[0][2] += a.x * b.z; acc[0][3] += a.x * b.w;
            acc[1][0] += a.y * b.x; acc[1][1] += a.y * b.y; acc[1][2] += a.y * b.z; acc[1][3] += a.y * b.w;
            acc[2][0] += a.z * b.x; acc[2][1] += a.z * b.y; acc[2][2] += a.z * b.z; acc[2][3] += a.z * b.w;
            acc[3][0] += a.w * b.x; acc[3][1] += a.w * b.y; acc[3][2] += a.w * b.z; acc[3][3] += a.w * b.w;
        }
        __syncthreads();
    }

    #pragma unroll
    for (int ii = 0; ii < 4; ii++) {
        #pragma unroll
        for (int jj = 0; jj < 4; jj++) {
            const int m = mBase + ty * 4 + ii;
            const int n = nBase + tx * 4 + jj;
            const float v = acc[ii][jj] + bias[n];
            if (MODE == 0) {
                C[(size_t)m * N + n] = v;
            } else {
                const int b  = m / LL, l = m % LL;
                const int h  = n / DKH, dk = n % DKH;
                C[(((size_t)b * HH + h) * LL + l) * DKH + dk] = v;
            }
        }
    }
}

// ----------------------------------------------------------------------------
// Causal flash attention, fp32, BQ=BKV=64, DK=64, 256 threads.
// Q,K,V: (B*H, L, DK). O written to (B, L, D).
// ----------------------------------------------------------------------------
#define ATTN_SMEM_FLOATS (3*64*65 + 64*64 + 3*64)
#define ATTN_SMEM_BYTES  (ATTN_SMEM_FLOATS * 4)

__global__ void attn_kernel(const float* __restrict__ Q, const float* __restrict__ Kp_,
                            const float* __restrict__ Vp_, float* __restrict__ O) {
    extern __shared__ float sm[];
    float (*sQ)[65] = (float(*)[65])(sm);              // padded: column access over d
    float (*sK)[65] = (float(*)[65])(sm + 4160);       // padded: column access over d
    float (*sS)[65] = (float(*)[65])(sm + 8320);       // padded: column access over j
    float (*sV)[64] = (float(*)[64])(sm + 12480);      // row access only
    float* sM  = sm + 12480 + 4096;
    float* sL  = sM + 64;
    float* sAl = sL + 64;

    const int tid = threadIdx.x;
    const int ty = tid >> 4, tx = tid & 15;
    const int i0 = ty * 4;          // query rows owned by this thread
    const int c0 = tx * 4;          // key-col / dk-col owned

    const int bh = blockIdx.y;
    const int qb = blockIdx.x;

    const float* Qp = Q + ((size_t)bh * LL + qb * 64) * DKH;

    for (int i = tid; i < 64 * 64; i += 256) sQ[i >> 6][i & 63] = Qp[i];
    if (tid < 64) { sM[tid] = -1e30f; sL[tid] = 0.0f; }

    float acc[4][4] = {};
    const float scale = 0.125f;   // 1/sqrt(64)
    __syncthreads();

    for (int kb = 0; kb <= qb; kb++) {
        const float* Kt = Kp_ + ((size_t)bh * LL + kb * 64) * DKH;
        const float* Vt = Vp_ + ((size_t)bh * LL + kb * 64) * DKH;
        for (int i = tid; i < 64 * 64; i += 256) {
            sK[i >> 6][i & 63] = Kt[i];
            sV[i >> 6][i & 63] = Vt[i];
        }
        __syncthreads();

        // S = Q K^T (scaled), with causal mask on diagonal tile
        float s[4][4] = {};
        #pragma unroll 8
        for (int d = 0; d < 64; d++) {
            float a0 = sQ[i0 + 0][d], a1 = sQ[i0 + 1][d], a2 = sQ[i0 + 2][d], a3 = sQ[i0 + 3][d];
            float b0 = sK[c0 + 0][d], b1 = sK[c0 + 1][d], b2 = sK[c0 + 2][d], b3 = sK[c0 + 3][d];
            s[0][0] += a0 * b0; s[0][1] += a0 * b1; s[0][2] += a0 * b2; s[0][3] += a0 * b3;
            s[1][0] += a1 * b0; s[1][1] += a1 * b1; s[1][2] += a1 * b2; s[1][3] += a1 * b3;
            s[2][0] += a2 * b0; s[2][1] += a2 * b1; s[2][2] += a2 * b2; s[2][3] += a2 * b3;
            s[3][0] += a3 * b0; s[3][1] += a3 * b1; s[3][2] += a3 * b2; s[3][3] += a3 * b3;
        }
        const bool diag = (kb == qb);
        #pragma unroll
        for (int ii = 0; ii < 4; ii++)
            #pragma unroll
            for (int jj = 0; jj < 4; jj++) {
                float v = s[ii][jj] * scale;
                if (diag && (c0 + jj) > (i0 + ii)) v = -1e30f;
                sS[i0 + ii][c0 + jj] = v;
            }
        __syncthreads();

        // row max + alpha (one thread per row)
        if (tid < 64) {
            float mOld = sM[tid];
            float mx = mOld;
            #pragma unroll 8
            for (int j = 0; j < 64; j++) mx = fmaxf(mx, sS[tid][j]);
            sM[tid] = mx;
            sAl[tid] = __expf(mOld - mx);
        }
        __syncthreads();

        // exponentiate in place
        #pragma unroll
        for (int ii = 0; ii < 4; ii++) {
            const float mrow = sM[i0 + ii];
            #pragma unroll
            for (int jj = 0; jj < 4; jj++)
                sS[i0 + ii][c0 + jj] = __expf(sS[i0 + ii][c0 + jj] - mrow);
        }
        __syncthreads();

        // row sum update (concurrent with O update below; disjoint data)
        if (tid < 64) {
            float sum = 0.0f;
            #pragma unroll 8
            for (int j = 0; j < 64; j++) sum += sS[tid][j];
            sL[tid] = sL[tid] * sAl[tid] + sum;
        }

        // O = O*alpha + P @ V
        float al[4];
        #pragma unroll
        for (int ii = 0; ii < 4; ii++) al[ii] = sAl[i0 + ii];
        #pragma unroll
        for (int ii = 0; ii < 4; ii++)
            #pragma unroll
            for (int jj = 0; jj < 4; jj++) acc[ii][jj] *= al[ii];

        #pragma unroll 8
        for (int j = 0; j < 64; j++) {
            float a0 = sS[i0 + 0][j], a1 = sS[i0 + 1][j], a2 = sS[i0 + 2][j], a3 = sS[i0 + 3][j];
            float b0 = sV[j][c0 + 0], b1 = sV[j][c0 + 1], b2 = sV[j][c0 + 2], b3 = sV[j][c0 + 3];
            acc[0][0] += a0 * b0; acc[0][1] += a0 * b1; acc[0][2] += a0 * b2; acc[0][3] += a0 * b3;
            acc[1][0] += a1 * b0; acc[1][1] += a1 * b1; acc[1][2] += a1 * b2; acc[1][3] += a1 * b3;
            acc[2][0] += a2 * b0; acc[2][1] += a2 * b1; acc[2][2] += a2 * b2; acc[2][3] += a2 * b3;
            acc[3][0] += a3 * b0; acc[3][1] += a3 * b1; acc[3][2] += a3 * b2; acc[3][3] += a3 * b3;
        }
        __syncthreads();   // protects sK/sV/sS/sM/sL/sAl for next iteration
    }

    // epilogue: normalize and scatter to (B, L, D)
    const int b = bh >> 4, h = bh & 15;
    float inv[4];
    #pragma unroll
    for (int ii = 0; ii < 4; ii++) inv[ii] = 1.0f / sL[i0 + ii];
    #pragma unroll
    for (int ii = 0; ii < 4; ii++) {
        const int l = qb * 64 + i0 + ii;
        float* orow = O + ((size_t)b * LL + l) * DD + h * DKH;
        #pragma unroll
        for (int jj = 0; jj < 4; jj++) orow[c0 + jj] = acc[ii][jj] * inv[ii];
    }
}

// ----------------------------------------------------------------------------
extern "C" void kernel_launch(void* const* d_in, const int* in_sizes, int n_in,
                              void* d_out, int out_size) {
    (void)in_sizes; (void)n_in; (void)out_size;
    const float* x  = (const float*)d_in[0];
    const float* wq = (const float*)d_in[1];
    const float* bq = (const float*)d_in[2];
    const float* wk = (const float*)d_in[3];
    const float* bk = (const float*)d_in[4];
    const float* wv = (const float*)d_in[5];
    const float* bv = (const float*)d_in[6];
    const float* wo = (const float*)d_in[7];
    const float* bo = (const float*)d_in[8];

    float *q, *k, *v, *o;
    cudaGetSymbolAddress((void**)&q, g_q);
    cudaGetSymbolAddress((void**)&k, g_k);
    cudaGetSymbolAddress((void**)&v, g_v);
    cudaGetSymbolAddress((void**)&o, g_o);

    dim3 gp(MTOT / 64, DD / 64);   // 64 x 16 blocks

    gemm64<1><<<gp, 256>>>(x, wq, bq, q, MTOT, DD, DD);
    gemm64<1><<<gp, 256>>>(x, wk, bk, k, MTOT, DD, DD);
    gemm64<1><<<gp, 256>>>(x, wv, bv, v, MTOT, DD, DD);

    cudaFuncSetAttribute(attn_kernel, cudaFuncAttributeMaxDynamicSharedMemorySize,
                         ATTN_SMEM_BYTES);
    attn_kernel<<<dim3(LL / 64, BB * HH), 256, ATTN_SMEM_BYTES>>>(q, k, v, o);

    gemm64<0><<<gp, 256>>>(o, wo, bo, (float*)d_out, MTOT, DD, DD);
}

// round 2
// speedup vs baseline: 1.1735x; 1.1735x over previous
#include <cuda_runtime.h>

// Problem constants (fixed by the reference)
#define BB 2
#define LL 2048
#define DD 1024
#define HH 16
#define DKH 64
#define MTOT (BB*LL)   // 4096

// Scratch (no cudaMalloc allowed)
__device__ float g_q[BB*HH*LL*DKH];
__device__ float g_k[BB*HH*LL*DKH];
__device__ float g_v[BB*HH*LL*DKH];
__device__ float g_o[BB*LL*DD];

// ----------------------------------------------------------------------------
// GEMM: C[m,n] = sum_k A[m,k]*W[n,k] + bias[n]   (nn.Linear: y = x@W^T + b)
// BM=BN=128, BK=16, 256 threads, 8x8 per thread (quadrant split), double buffer.
// MODE 0: C row-major MxN. MODE 1: scatter to (B,H,L,DK).
// ----------------------------------------------------------------------------
template<int MODE>
__global__ void __launch_bounds__(256, 2) gemm128(
        const float* __restrict__ A, const float* __restrict__ W,
        const float* __restrict__ bias, float* __restrict__ C,
        int M, int N, int K) {
    __shared__ float sA[2][16][128];   // [k][m]
    __shared__ float sB[2][16][128];   // [k][n]

    const int tid = threadIdx.x;
    const int tx = tid & 15, ty = tid >> 4;
    const int mBase = blockIdx.x * 128, nBase = blockIdx.y * 128;

    // loader mapping: each thread loads 8 floats (2x float4) per matrix per stage
    const int lr = tid >> 1;              // 0..127 row in tile
    const int lk = (tid & 1) * 8;         // 0 or 8

    const float* Ap = A + (size_t)(mBase + lr) * K + lk;
    const float* Wp = W + (size_t)(nBase + lr) * K + lk;

    float acc[8][8] = {};

    float4 pa0 = *(const float4*)(Ap);
    float4 pa1 = *(const float4*)(Ap + 4);
    float4 pb0 = *(const float4*)(Wp);
    float4 pb1 = *(const float4*)(Wp + 4);

    // store stage 0
    sA[0][lk+0][lr]=pa0.x; sA[0][lk+1][lr]=pa0.y; sA[0][lk+2][lr]=pa0.z; sA[0][lk+3][lr]=pa0.w;
    sA[0][lk+4][lr]=pa1.x; sA[0][lk+5][lr]=pa1.y; sA[0][lk+6][lr]=pa1.z; sA[0][lk+7][lr]=pa1.w;
    sB[0][lk+0][lr]=pb0.x; sB[0][lk+1][lr]=pb0.y; sB[0][lk+2][lr]=pb0.z; sB[0][lk+3][lr]=pb0.w;
    sB[0][lk+4][lr]=pb1.x; sB[0][lk+5][lr]=pb1.y; sB[0][lk+6][lr]=pb1.z; sB[0][lk+7][lr]=pb1.w;
    __syncthreads();

    int buf = 0;
    for (int k0 = 16; k0 <= K; k0 += 16) {
        const bool more = (k0 < K);
        if (more) {
            pa0 = *(const float4*)(Ap + k0);
            pa1 = *(const float4*)(Ap + k0 + 4);
            pb0 = *(const float4*)(Wp + k0);
            pb1 = *(const float4*)(Wp + k0 + 4);
        }
        #pragma unroll
        for (int k = 0; k < 16; k++) {
            float4 a0 = *(const float4*)&sA[buf][k][ty * 4];
            float4 a1 = *(const float4*)&sA[buf][k][ty * 4 + 64];
            float4 b0 = *(const float4*)&sB[buf][k][tx * 4];
            float4 b1 = *(const float4*)&sB[buf][k][tx * 4 + 64];
            float av[8] = {a0.x,a0.y,a0.z,a0.w,a1.x,a1.y,a1.z,a1.w};
            float bv[8] = {b0.x,b0.y,b0.z,b0.w,b1.x,b1.y,b1.z,b1.w};
            #pragma unroll
            for (int ii = 0; ii < 8; ii++)
                #pragma unroll
                for (int jj = 0; jj < 8; jj++)
                    acc[ii][jj] += av[ii] * bv[jj];
        }
        if (more) {
            const int nb = buf ^ 1;
            sA[nb][lk+0][lr]=pa0.x; sA[nb][lk+1][lr]=pa0.y; sA[nb][lk+2][lr]=pa0.z; sA[nb][lk+3][lr]=pa0.w;
            sA[nb][lk+4][lr]=pa1.x; sA[nb][lk+5][lr]=pa1.y; sA[nb][lk+6][lr]=pa1.z; sA[nb][lk+7][lr]=pa1.w;
            sB[nb][lk+0][lr]=pb0.x; sB[nb][lk+1][lr]=pb0.y; sB[nb][lk+2][lr]=pb0.z; sB[nb][lk+3][lr]=pb0.w;
            sB[nb][lk+4][lr]=pb1.x; sB[nb][lk+5][lr]=pb1.y; sB[nb][lk+6][lr]=pb1.z; sB[nb][lk+7][lr]=pb1.w;
        }
        __syncthreads();
        buf ^= 1;
    }

    #pragma unroll
    for (int ih = 0; ih < 2; ih++) {
        #pragma unroll
        for (int ii = 0; ii < 4; ii++) {
            const int m = mBase + ty * 4 + ih * 64 + ii;
            #pragma unroll
            for (int jh = 0; jh < 2; jh++) {
                const int n = nBase + tx * 4 + jh * 64;
                float4 bv = *(const float4*)(bias + n);
                float4 v;
                v.x = acc[ih*4+ii][jh*4+0] + bv.x;
                v.y = acc[ih*4+ii][jh*4+1] + bv.y;
                v.z = acc[ih*4+ii][jh*4+2] + bv.z;
                v.w = acc[ih*4+ii][jh*4+3] + bv.w;
                if (MODE == 0) {
                    *(float4*)(C + (size_t)m * N + n) = v;
                } else {
                    const int b = m / LL, l = m % LL;
                    const int h = n / DKH, dk = n % DKH;
                    *(float4*)(C + (((size_t)b * HH + h) * LL + l) * DKH + dk) = v;
                }
            }
        }
    }
}

// ----------------------------------------------------------------------------
// Causal flash attention: BQ=128, BKV=64, DK=64, 256 threads, 8x4 thread tile.
// Register-resident softmax state (m,l,O) with 16-lane shuffle reductions.
// Q,K,V: (B*H, L, DK). O written to (B, L, D).
// ----------------------------------------------------------------------------
#define BQ 128
#define SQT_S 132
#define SKT_S 68
#define SP_S  68
#define ATTN_SMEM_FLOATS (64*SQT_S + 64*SKT_S + 64*64 + 128*SP_S)   // 25600
#define ATTN_SMEM_BYTES  (ATTN_SMEM_FLOATS * 4)                      // 100 KB

__global__ void __launch_bounds__(256) attn_kernel(
        const float* __restrict__ Q, const float* __restrict__ Kg,
        const float* __restrict__ Vg, float* __restrict__ O) {
    extern __shared__ float sm[];
    float (*sQT)[SQT_S] = (float(*)[SQT_S])sm;                            // [64][132]
    float (*sKT)[SKT_S] = (float(*)[SKT_S])(sm + 64*SQT_S);               // [64][68]
    float (*sV)[64]     = (float(*)[64])(sm + 64*SQT_S + 64*SKT_S);       // [64][64]
    float (*sP)[SP_S]   = (float(*)[SP_S])(sm + 64*SQT_S + 64*SKT_S + 64*64); // [128][68]

    const int tid = threadIdx.x;
    const int tx = tid & 15, ty = tid >> 4;
    const int qb = blockIdx.x, bh = blockIdx.y;

    // Load Q tile transposed: sQT[dk][l]
    {
        const int l = tid & 127;
        const int dk0 = (tid >> 7) * 32;
        const float* Qp = Q + ((size_t)bh * LL + qb * BQ + l) * DKH + dk0;
        #pragma unroll
        for (int t = 0; t < 8; t++) {
            float4 qv = *(const float4*)(Qp + t * 4);
            const int dk = dk0 + t * 4;
            sQT[dk+0][l] = qv.x; sQT[dk+1][l] = qv.y;
            sQT[dk+2][l] = qv.z; sQT[dk+3][l] = qv.w;
        }
    }

    float o[8][4] = {};
    float mrow[8], lrow[8];
    #pragma unroll
    for (int r = 0; r < 8; r++) { mrow[r] = -1e30f; lrow[r] = 0.0f; }

    const int jload = tid & 63;
    const int dload = (tid >> 6) * 16;
    const float* Kbase = Kg + (size_t)bh * LL * DKH;
    const float* Vbase = Vg + (size_t)bh * LL * DKH;
    const int kbmax = 2 * qb + 1;
    const float scale = 0.125f;   // 1/sqrt(64)

    __syncthreads();

    for (int kb = 0; kb <= kbmax; kb++) {
        // Load K (transposed) and V tiles
        {
            const float* Kt = Kbase + (size_t)(kb * 64 + jload) * DKH + dload;
            const float* Vt = Vbase + (size_t)(kb * 64 + jload) * DKH + dload;
            #pragma unroll
            for (int t = 0; t < 4; t++) {
                const int dk = dload + t * 4;
                float4 kv = *(const float4*)(Kt + t * 4);
                sKT[dk+0][jload] = kv.x; sKT[dk+1][jload] = kv.y;
                sKT[dk+2][jload] = kv.z; sKT[dk+3][jload] = kv.w;
                float4 vv = *(const float4*)(Vt + t * 4);
                *(float4*)&sV[jload][dk] = vv;
            }
        }
        __syncthreads();

        // S = Q K^T over d (3x LDS.128 per 32 FMA)
        float s[8][4] = {};
        #pragma unroll 8
        for (int d = 0; d < 64; d++) {
            float4 q0 = *(const float4*)&sQT[d][ty * 4];
            float4 q1 = *(const float4*)&sQT[d][ty * 4 + 64];
            float4 kv = *(const float4*)&sKT[d][tx * 4];
            float qa[8] = {q0.x,q0.y,q0.z,q0.w,q1.x,q1.y,q1.z,q1.w};
            #pragma unroll
            for (int r = 0; r < 8; r++) {
                s[r][0] += qa[r] * kv.x; s[r][1] += qa[r] * kv.y;
                s[r][2] += qa[r] * kv.z; s[r][3] += qa[r] * kv.w;
            }
        }

        const bool needMask = (kb >= 2 * qb);

        // Register softmax with 16-lane butterflies (row group == half-warp)
        #pragma unroll
        for (int r = 0; r < 8; r++) {
            const int rl = ty * 4 + (r >> 2) * 64 + (r & 3);
            const int ig = qb * BQ + rl;
            float vmax = -1e30f;
            #pragma unroll
            for (int c = 0; c < 4; c++) {
                float v = s[r][c] * scale;
                if (needMask) {
                    const int jg = kb * 64 + tx * 4 + c;
                    if (jg > ig) v = -1e30f;
                }
                s[r][c] = v;
                vmax = fmaxf(vmax, v);
            }
            #pragma unroll
            for (int w = 1; w < 16; w <<= 1)
                vmax = fmaxf(vmax, __shfl_xor_sync(0xffffffffu, vmax, w));
            const float mnew = fmaxf(mrow[r], vmax);
            const float alpha = __expf(mrow[r] - mnew);
            mrow[r] = mnew;
            float rs = 0.0f;
            #pragma unroll
            for (int c = 0; c < 4; c++) {
                const float p = __expf(s[r][c] - mnew);
                s[r][c] = p;
                rs += p;
            }
            #pragma unroll
            for (int w = 1; w < 16; w <<= 1)
                rs += __shfl_xor_sync(0xffffffffu, rs, w);
            lrow[r] = lrow[r] * alpha + rs;
            #pragma unroll
            for (int c = 0; c < 4; c++) o[r][c] *= alpha;
            *(float4*)&sP[rl][tx * 4] = make_float4(s[r][0], s[r][1], s[r][2], s[r][3]);
        }
        __syncthreads();

        // O += P @ V
        #pragma unroll 4
        for (int j = 0; j < 64; j++) {
            float4 v4 = *(const float4*)&sV[j][tx * 4];
            #pragma unroll
            for (int r = 0; r < 8; r++) {
                const int rl = ty * 4 + (r >> 2) * 64 + (r & 3);
                const float p = sP[rl][j];
                o[r][0] += p * v4.x; o[r][1] += p * v4.y;
                o[r][2] += p * v4.z; o[r][3] += p * v4.w;
            }
        }
        __syncthreads();   // protect sKT/sV/sP before next tile load
    }

    // Epilogue: normalize, scatter to (B, L, D)
    const int b = bh >> 4, h = bh & 15;
    #pragma unroll
    for (int r = 0; r < 8; r++) {
        const int rl = ty * 4 + (r >> 2) * 64 + (r & 3);
        const int lg = qb * BQ + rl;
        const float inv = 1.0f / lrow[r];
        float4 v = make_float4(o[r][0]*inv, o[r][1]*inv, o[r][2]*inv, o[r][3]*inv);
        *(float4*)(O + ((size_t)b * LL + lg) * DD + h * DKH + tx * 4) = v;
    }
}

// ----------------------------------------------------------------------------
extern "C" void kernel_launch(void* const* d_in, const int* in_sizes, int n_in,
                              void* d_out, int out_size) {
    (void)in_sizes; (void)n_in; (void)out_size;
    const float* x  = (const float*)d_in[0];
    const float* wq = (const float*)d_in[1];
    const float* bq = (const float*)d_in[2];
    const float* wk = (const float*)d_in[3];
    const float* bk = (const float*)d_in[4];
    const float* wv = (const float*)d_in[5];
    const float* bv = (const float*)d_in[6];
    const float* wo = (const float*)d_in[7];
    const float* bo = (const float*)d_in[8];

    float *q, *k, *v, *o;
    cudaGetSymbolAddress((void**)&q, g_q);
    cudaGetSymbolAddress((void**)&k, g_k);
    cudaGetSymbolAddress((void**)&v, g_v);
    cudaGetSymbolAddress((void**)&o, g_o);

    dim3 gp(MTOT / 128, DD / 128);   // 32 x 8 blocks

    gemm128<1><<<gp, 256>>>(x, wq, bq, q, MTOT, DD, DD);
    gemm128<1><<<gp, 256>>>(x, wk, bk, k, MTOT, DD, DD);
    gemm128<1><<<gp, 256>>>(x, wv, bv, v, MTOT, DD, DD);

    cudaFuncSetAttribute(attn_kernel, cudaFuncAttributeMaxDynamicSharedMemorySize,
                         ATTN_SMEM_BYTES);
    attn_kernel<<<dim3(LL / BQ, BB * HH), 256, ATTN_SMEM_BYTES>>>(q, k, v, o);

    gemm128<0><<<gp, 256>>>(o, wo, bo, (float*)d_out, MTOT, DD, DD);
}

// round 4
// speedup vs baseline: 1.6826x; 1.4338x over previous
#include <cuda_runtime.h>
#include <cuda_bf16.h>
#include <cstdint>

// Problem constants
#define BB 2
#define LL 2048
#define DD 1024
#define HH 16
#define DKH 64
#define MTOT (BB*LL)   // 4096

// ---------------------------------------------------------------------------
// Scratch (no cudaMalloc allowed)
// ---------------------------------------------------------------------------
__device__ float g_q[BB*HH*LL*DKH];
__device__ float g_k[BB*HH*LL*DKH];
__device__ float g_v[BB*HH*LL*DKH];
__device__ float g_o[BB*LL*DD];
__device__ __nv_bfloat16 g_xhi[MTOT*DD], g_xlo[MTOT*DD];
__device__ __nv_bfloat16 g_whi[4*DD*DD], g_wlo[4*DD*DD];
__device__ __nv_bfloat16 g_ohi[MTOT*DD], g_olo[MTOT*DD];

__device__ __forceinline__ uint32_t smem_to_u32(const void* p) {
    uint32_t a;
    asm("{ .reg .u64 t; cvta.to.shared.u64 t, %1; cvt.u32.u64 %0, t; }" : "=r"(a) : "l"(p));
    return a;
}
#define SMEM_SWIZZLE_128B(o) ((o) ^ (((o) >> 3) & 0x70))

__device__ __forceinline__ void ldmx4(uint32_t* r, uint32_t addr) {
    asm volatile("ldmatrix.sync.aligned.m8n8.x4.shared.b16 {%0,%1,%2,%3}, [%4];"
                 : "=r"(r[0]), "=r"(r[1]), "=r"(r[2]), "=r"(r[3]) : "r"(addr));
}
__device__ __forceinline__ void mma_bf16(float* c, const uint32_t* a, const uint32_t* b) {
    asm volatile("mma.sync.aligned.m16n8k16.row.col.f32.bf16.bf16.f32 "
                 "{%0,%1,%2,%3}, {%4,%5,%6,%7}, {%8,%9}, {%0,%1,%2,%3};"
                 : "+f"(c[0]), "+f"(c[1]), "+f"(c[2]), "+f"(c[3])
                 : "r"(a[0]), "r"(a[1]), "r"(a[2]), "r"(a[3]), "r"(b[0]), "r"(b[1]));
}

// ---------------------------------------------------------------------------
// fp32 -> bf16 hi/lo split
// ---------------------------------------------------------------------------
__global__ void split_kernel(const float* __restrict__ src,
                             __nv_bfloat16* __restrict__ hi,
                             __nv_bfloat16* __restrict__ lo, int n4) {
    int i = blockIdx.x * blockDim.x + threadIdx.x;
    if (i >= n4) return;
    float4 v = ((const float4*)src)[i];
    __nv_bfloat16 h0 = __float2bfloat16(v.x), h1 = __float2bfloat16(v.y);
    __nv_bfloat16 h2 = __float2bfloat16(v.z), h3 = __float2bfloat16(v.w);
    __nv_bfloat16 l0 = __float2bfloat16(v.x - __bfloat162float(h0));
    __nv_bfloat16 l1 = __float2bfloat16(v.y - __bfloat162float(h1));
    __nv_bfloat16 l2 = __float2bfloat16(v.z - __bfloat162float(h2));
    __nv_bfloat16 l3 = __float2bfloat16(v.w - __bfloat162float(h3));
    ((__nv_bfloat162*)hi)[i*2+0] = __nv_bfloat162(h0, h1);
    ((__nv_bfloat162*)hi)[i*2+1] = __nv_bfloat162(h2, h3);
    ((__nv_bfloat162*)lo)[i*2+0] = __nv_bfloat162(l0, l1);
    ((__nv_bfloat162*)lo)[i*2+1] = __nv_bfloat162(l2, l3);
}

// ---------------------------------------------------------------------------
// mma.sync bf16 GEMM, 3-term split: C = Ahi*Bhi^T + Ahi*Blo^T + Alo*Bhi^T + bias
// CTA tile 128x128, K-chunk 64 (SW128 smem), 8 warps (2 M x 4 N), warp 64x32.
// MODE 0: C row-major MxN. MODE 1: scatter to (B,H,L,DK).
// ---------------------------------------------------------------------------
#define TCG_SMEM (4*16384)

template<int MODE>
__global__ void __launch_bounds__(256, 2) mm_gemm(
        const __nv_bfloat16* __restrict__ Ahi, const __nv_bfloat16* __restrict__ Alo,
        const __nv_bfloat16* __restrict__ Bhi, const __nv_bfloat16* __restrict__ Blo,
        const float* __restrict__ bias, float* __restrict__ C,
        int M, int N, int K) {
    extern __shared__ char sm[];
    const uint32_t sbase = smem_to_u32(sm);

    const int tid  = threadIdx.x;
    const int wid  = tid >> 5, lane = tid & 31;
    const int wm   = wid & 1, wn = wid >> 1;          // 2 x 4 warp grid
    const int mBase = blockIdx.x * 128, nBase = blockIdx.y * 128;

    float acc[4][4][4] = {};   // [mf][nf][reg]

    // loader: 4 tiles x 128 rows x 8 segs(16B) = 4096 float4 / 256 thr = 16 iters
    // tile order: 0=Ahi 1=Alo 2=Bhi 3=Blo
    // A-frag lane addressing (invariant parts)
    const int aRow = (lane & 15);              // + wm*64 + mf*16
    const int aKb  = (lane >> 4) * 16;         // byte offset within kstep
    // B-frag lane addressing
    const int bRow = ((lane >> 4) & 1) * 8 + (lane & 7);   // + wn*32 + p*16
    const int bKb  = ((lane >> 3) & 1) * 16;

    for (int k0 = 0; k0 < K; k0 += 64) {
        #pragma unroll
        for (int it = 0; it < 16; it++) {
            const int u = it * 256 + tid;
            const int t = u >> 10, idx = u & 1023;
            const int row = idx >> 3, seg = idx & 7;
            const __nv_bfloat16* g;
            if      (t == 0) g = Ahi + (size_t)(mBase + row) * K;
            else if (t == 1) g = Alo + (size_t)(mBase + row) * K;
            else if (t == 2) g = Bhi + (size_t)(nBase + row) * K;
            else             g = Blo + (size_t)(nBase + row) * K;
            float4 v = *(const float4*)(g + k0 + seg * 8);
            const uint32_t sw = SMEM_SWIZZLE_128B(row * 128 + seg * 16);
            *(float4*)(sm + t * 16384 + sw) = v;
        }
        __syncthreads();

        #pragma unroll
        for (int ks = 0; ks < 4; ks++) {
            // B fragments: hi & lo, 2 x4-loads each covering n-frag pairs
            uint32_t bh[4][2], bl[4][2];
            #pragma unroll
            for (int p = 0; p < 2; p++) {
                const uint32_t boff = SMEM_SWIZZLE_128B(
                    (wn * 32 + p * 16 + bRow) * 128 + ks * 32 + bKb);
                uint32_t r[4];
                ldmx4(r, sbase + 2*16384 + boff);
                bh[p*2+0][0] = r[0]; bh[p*2+0][1] = r[1];
                bh[p*2+1][0] = r[2]; bh[p*2+1][1] = r[3];
                ldmx4(r, sbase + 3*16384 + boff);
                bl[p*2+0][0] = r[0]; bl[p*2+0][1] = r[1];
                bl[p*2+1][0] = r[2]; bl[p*2+1][1] = r[3];
            }
            #pragma unroll
            for (int mf = 0; mf < 4; mf++) {
                const uint32_t aoff = SMEM_SWIZZLE_128B(
                    (wm * 64 + mf * 16 + aRow) * 128 + ks * 32 + aKb);
                uint32_t ah[4], al[4];
                ldmx4(ah, sbase + 0*16384 + aoff);
                ldmx4(al, sbase + 1*16384 + aoff);
                #pragma unroll
                for (int nf = 0; nf < 4; nf++) {
                    mma_bf16(acc[mf][nf], ah, bh[nf]);
                    mma_bf16(acc[mf][nf], ah, bl[nf]);
                    mma_bf16(acc[mf][nf], al, bh[nf]);
                }
            }
        }
        __syncthreads();
    }

    // Epilogue: d0,d1 @ (row, col), d2,d3 @ (row+8, col); col = 2*(lane&3)
    const int rEp = lane >> 2, cEp = (lane & 3) * 2;
    #pragma unroll
    for (int mf = 0; mf < 4; mf++) {
        #pragma unroll
        for (int nf = 0; nf < 4; nf++) {
            const int m0 = mBase + wm * 64 + mf * 16 + rEp;
            const int n  = nBase + wn * 32 + nf * 8 + cEp;
            const float b0 = bias[n], b1 = bias[n + 1];
            float2 v0 = make_float2(acc[mf][nf][0] + b0, acc[mf][nf][1] + b1);
            float2 v1 = make_float2(acc[mf][nf][2] + b0, acc[mf][nf][3] + b1);
            if (MODE == 0) {
                *(float2*)(C + (size_t)m0 * N + n) = v0;
                *(float2*)(C + (size_t)(m0 + 8) * N + n) = v1;
            } else {
                const int h = n >> 6, dk = n & 63;
                const int b_ = m0 / LL, l0 = m0 % LL;
                const int l1 = (m0 + 8) % LL;   // same b (tiles never straddle LL)
                *(float2*)(C + (((size_t)b_ * HH + h) * LL + l0) * DKH + dk) = v0;
                *(float2*)(C + (((size_t)b_ * HH + h) * LL + l1) * DKH + dk) = v1;
            }
        }
    }
}

// ---------------------------------------------------------------------------
// Causal flash attention (unchanged from R2): BQ=128, BKV=64, 256 threads.
// ---------------------------------------------------------------------------
#define BQ 128
#define SQT_S 132
#define SKT_S 68
#define SP_S  68
#define ATTN_SMEM_FLOATS (64*SQT_S + 64*SKT_S + 64*64 + 128*SP_S)
#define ATTN_SMEM_BYTES  (ATTN_SMEM_FLOATS * 4)

__global__ void __launch_bounds__(256) attn_kernel(
        const float* __restrict__ Q, const float* __restrict__ Kg,
        const float* __restrict__ Vg, float* __restrict__ O) {
    extern __shared__ float smf[];
    float (*sQT)[SQT_S] = (float(*)[SQT_S])smf;
    float (*sKT)[SKT_S] = (float(*)[SKT_S])(smf + 64*SQT_S);
    float (*sV)[64]     = (float(*)[64])(smf + 64*SQT_S + 64*SKT_S);
    float (*sP)[SP_S]   = (float(*)[SP_S])(smf + 64*SQT_S + 64*SKT_S + 64*64);

    const int tid = threadIdx.x;
    const int tx = tid & 15, ty = tid >> 4;
    const int qb = blockIdx.x, bh = blockIdx.y;

    {
        const int l = tid & 127;
        const int dk0 = (tid >> 7) * 32;
        const float* Qp = Q + ((size_t)bh * LL + qb * BQ + l) * DKH + dk0;
        #pragma unroll
        for (int t = 0; t < 8; t++) {
            float4 qv = *(const float4*)(Qp + t * 4);
            const int dk = dk0 + t * 4;
            sQT[dk+0][l] = qv.x; sQT[dk+1][l] = qv.y;
            sQT[dk+2][l] = qv.z; sQT[dk+3][l] = qv.w;
        }
    }

    float o[8][4] = {};
    float mrow[8], lrow[8];
    #pragma unroll
    for (int r = 0; r < 8; r++) { mrow[r] = -1e30f; lrow[r] = 0.0f; }

    const int jload = tid & 63;
    const int dload = (tid >> 6) * 16;
    const float* Kbase = Kg + (size_t)bh * LL * DKH;
    const float* Vbase = Vg + (size_t)bh * LL * DKH;
    const int kbmax = 2 * qb + 1;
    const float scale = 0.125f;

    __syncthreads();

    for (int kb = 0; kb <= kbmax; kb++) {
        {
            const float* Kt = Kbase + (size_t)(kb * 64 + jload) * DKH + dload;
            const float* Vt = Vbase + (size_t)(kb * 64 + jload) * DKH + dload;
            #pragma unroll
            for (int t = 0; t < 4; t++) {
                const int dk = dload + t * 4;
                float4 kv = *(const float4*)(Kt + t * 4);
                sKT[dk+0][jload] = kv.x; sKT[dk+1][jload] = kv.y;
                sKT[dk+2][jload] = kv.z; sKT[dk+3][jload] = kv.w;
                float4 vv = *(const float4*)(Vt + t * 4);
                *(float4*)&sV[jload][dk] = vv;
            }
        }
        __syncthreads();

        float s[8][4] = {};
        #pragma unroll 8
        for (int d = 0; d < 64; d++) {
            float4 q0 = *(const float4*)&sQT[d][ty * 4];
            float4 q1 = *(const float4*)&sQT[d][ty * 4 + 64];
            float4 kv = *(const float4*)&sKT[d][tx * 4];
            float qa[8] = {q0.x,q0.y,q0.z,q0.w,q1.x,q1.y,q1.z,q1.w};
            #pragma unroll
            for (int r = 0; r < 8; r++) {
                s[r][0] += qa[r] * kv.x; s[r][1] += qa[r] * kv.y;
                s[r][2] += qa[r] * kv.z; s[r][3] += qa[r] * kv.w;
            }
        }

        const bool needMask = (kb >= 2 * qb);

        #pragma unroll
        for (int r = 0; r < 8; r++) {
            const int rl = ty * 4 + (r >> 2) * 64 + (r & 3);
            const int ig = qb * BQ + rl;
            float vmax = -1e30f;
            #pragma unroll
            for (int c = 0; c < 4; c++) {
                float v = s[r][c] * scale;
                if (needMask) {
                    const int jg = kb * 64 + tx * 4 + c;
                    if (jg > ig) v = -1e30f;
                }
                s[r][c] = v;
                vmax = fmaxf(vmax, v);
            }
            #pragma unroll
            for (int w = 1; w < 16; w <<= 1)
                vmax = fmaxf(vmax, __shfl_xor_sync(0xffffffffu, vmax, w));
            const float mnew = fmaxf(mrow[r], vmax);
            const float alpha = __expf(mrow[r] - mnew);
            mrow[r] = mnew;
            float rs = 0.0f;
            #pragma unroll
            for (int c = 0; c < 4; c++) {
                const float p = __expf(s[r][c] - mnew);
                s[r][c] = p;
                rs += p;
            }
            #pragma unroll
            for (int w = 1; w < 16; w <<= 1)
                rs += __shfl_xor_sync(0xffffffffu, rs, w);
            lrow[r] = lrow[r] * alpha + rs;
            #pragma unroll
            for (int c = 0; c < 4; c++) o[r][c] *= alpha;
            *(float4*)&sP[rl][tx * 4] = make_float4(s[r][0], s[r][1], s[r][2], s[r][3]);
        }
        __syncthreads();

        #pragma unroll 4
        for (int j = 0; j < 64; j++) {
            float4 v4 = *(const float4*)&sV[j][tx * 4];
            #pragma unroll
            for (int r = 0; r < 8; r++) {
                const int rl = ty * 4 + (r >> 2) * 64 + (r & 3);
                const float p = sP[rl][j];
                o[r][0] += p * v4.x; o[r][1] += p * v4.y;
                o[r][2] += p * v4.z; o[r][3] += p * v4.w;
            }
        }
        __syncthreads();
    }

    const int b = bh >> 4, h = bh & 15;
    #pragma unroll
    for (int r = 0; r < 8; r++) {
        const int rl = ty * 4 + (r >> 2) * 64 + (r & 3);
        const int lg = qb * BQ + rl;
        const float inv = 1.0f / lrow[r];
        float4 v = make_float4(o[r][0]*inv, o[r][1]*inv, o[r][2]*inv, o[r][3]*inv);
        *(float4*)(O + ((size_t)b * LL + lg) * DD + h * DKH + tx * 4) = v;
    }
}

// ---------------------------------------------------------------------------
extern "C" void kernel_launch(void* const* d_in, const int* in_sizes, int n_in,
                              void* d_out, int out_size) {
    (void)in_sizes; (void)n_in; (void)out_size;
    const float* x  = (const float*)d_in[0];
    const float* wq = (const float*)d_in[1];
    const float* bq = (const float*)d_in[2];
    const float* wk = (const float*)d_in[3];
    const float* bk = (const float*)d_in[4];
    const float* wv = (const float*)d_in[5];
    const float* bv = (const float*)d_in[6];
    const float* wo = (const float*)d_in[7];
    const float* bo = (const float*)d_in[8];

    float *q, *k, *v, *o;
    __nv_bfloat16 *xhi, *xlo, *whi, *wlo, *ohi, *olo;
    cudaGetSymbolAddress((void**)&q, g_q);
    cudaGetSymbolAddress((void**)&k, g_k);
    cudaGetSymbolAddress((void**)&v, g_v);
    cudaGetSymbolAddress((void**)&o, g_o);
    cudaGetSymbolAddress((void**)&xhi, g_xhi);
    cudaGetSymbolAddress((void**)&xlo, g_xlo);
    cudaGetSymbolAddress((void**)&whi, g_whi);
    cudaGetSymbolAddress((void**)&wlo, g_wlo);
    cudaGetSymbolAddress((void**)&ohi, g_ohi);
    cudaGetSymbolAddress((void**)&olo, g_olo);

    const int nx4 = MTOT * DD / 4;
    const int nw4 = DD * DD / 4;
    split_kernel<<<nx4 / 256, 256>>>(x, xhi, xlo, nx4);
    split_kernel<<<nw4 / 256, 256>>>(wq, whi + 0*DD*DD, wlo + 0*DD*DD, nw4);
    split_kernel<<<nw4 / 256, 256>>>(wk, whi + 1*DD*DD, wlo + 1*DD*DD, nw4);
    split_kernel<<<nw4 / 256, 256>>>(wv, whi + 2*DD*DD, wlo + 2*DD*DD, nw4);
    split_kernel<<<nw4 / 256, 256>>>(wo, whi + 3*DD*DD, wlo + 3*DD*DD, nw4);

    cudaFuncSetAttribute(mm_gemm<0>, cudaFuncAttributeMaxDynamicSharedMemorySize, TCG_SMEM);
    cudaFuncSetAttribute(mm_gemm<1>, cudaFuncAttributeMaxDynamicSharedMemorySize, TCG_SMEM);

    dim3 gp(MTOT / 128, DD / 128);   // 32 x 8

    mm_gemm<1><<<gp, 256, TCG_SMEM>>>(xhi, xlo, whi + 0*DD*DD, wlo + 0*DD*DD, bq, q, MTOT, DD, DD);
    mm_gemm<1><<<gp, 256, TCG_SMEM>>>(xhi, xlo, whi + 1*DD*DD, wlo + 1*DD*DD, bk, k, MTOT, DD, DD);
    mm_gemm<1><<<gp, 256, TCG_SMEM>>>(xhi, xlo, whi + 2*DD*DD, wlo + 2*DD*DD, bv, v, MTOT, DD, DD);

    cudaFuncSetAttribute(attn_kernel, cudaFuncAttributeMaxDynamicSharedMemorySize,
                         ATTN_SMEM_BYTES);
    attn_kernel<<<dim3(LL / BQ, BB * HH), 256, ATTN_SMEM_BYTES>>>(q, k, v, o);

    split_kernel<<<nx4 / 256, 256>>>(o, ohi, olo, nx4);
    mm_gemm<0><<<gp, 256, TCG_SMEM>>>(ohi, olo, whi + 3*DD*DD, wlo + 3*DD*DD, bo, (float*)d_out, MTOT, DD, DD);
}

// round 5
// speedup vs baseline: 3.1852x; 1.8930x over previous
#include <cuda_runtime.h>
#include <cuda_bf16.h>
#include <cstdint>

// Problem constants
#define BB 2
#define LL 2048
#define DD 1024
#define HH 16
#define DKH 64
#define MTOT (BB*LL)   // 4096

// ---------------------------------------------------------------------------
// Scratch (no cudaMalloc allowed) — all bf16 hi/lo split pairs
// ---------------------------------------------------------------------------
__device__ __nv_bfloat16 g_xhi[MTOT*DD], g_xlo[MTOT*DD];
__device__ __nv_bfloat16 g_whi[4*DD*DD], g_wlo[4*DD*DD];
__device__ __nv_bfloat16 g_qhi[BB*HH*LL*DKH], g_qlo[BB*HH*LL*DKH];
__device__ __nv_bfloat16 g_khi[BB*HH*LL*DKH], g_klo[BB*HH*LL*DKH];
__device__ __nv_bfloat16 g_vhi[BB*HH*LL*DKH], g_vlo[BB*HH*LL*DKH];
__device__ __nv_bfloat16 g_ohi[MTOT*DD], g_olo[MTOT*DD];

__device__ __forceinline__ uint32_t smem_to_u32(const void* p) {
    uint32_t a;
    asm("{ .reg .u64 t; cvta.to.shared.u64 t, %1; cvt.u32.u64 %0, t; }" : "=r"(a) : "l"(p));
    return a;
}
#define SMEM_SWIZZLE_128B(o) ((o) ^ (((o) >> 3) & 0x70))

__device__ __forceinline__ void ldmx4(uint32_t* r, uint32_t addr) {
    asm volatile("ldmatrix.sync.aligned.m8n8.x4.shared.b16 {%0,%1,%2,%3}, [%4];"
                 : "=r"(r[0]), "=r"(r[1]), "=r"(r[2]), "=r"(r[3]) : "r"(addr));
}
__device__ __forceinline__ void ldmx4t(uint32_t* r, uint32_t addr) {
    asm volatile("ldmatrix.sync.aligned.m8n8.x4.trans.shared.b16 {%0,%1,%2,%3}, [%4];"
                 : "=r"(r[0]), "=r"(r[1]), "=r"(r[2]), "=r"(r[3]) : "r"(addr));
}
__device__ __forceinline__ void mma_bf16(float* c, const uint32_t* a, const uint32_t* b) {
    asm volatile("mma.sync.aligned.m16n8k16.row.col.f32.bf16.bf16.f32 "
                 "{%0,%1,%2,%3}, {%4,%5,%6,%7}, {%8,%9}, {%0,%1,%2,%3};"
                 : "+f"(c[0]), "+f"(c[1]), "+f"(c[2]), "+f"(c[3])
                 : "r"(a[0]), "r"(a[1]), "r"(a[2]), "r"(a[3]), "r"(b[0]), "r"(b[1]));
}
__device__ __forceinline__ uint32_t pack_bf16(__nv_bfloat16 x, __nv_bfloat16 y) {
    __nv_bfloat162 h; h.x = x; h.y = y;
    uint32_t u; __builtin_memcpy(&u, &h, 4);
    return u;
}

// ---------------------------------------------------------------------------
// fp32 -> bf16 hi/lo split
// ---------------------------------------------------------------------------
__global__ void split_kernel(const float* __restrict__ src,
                             __nv_bfloat16* __restrict__ hi,
                             __nv_bfloat16* __restrict__ lo, int n4) {
    int i = blockIdx.x * blockDim.x + threadIdx.x;
    if (i >= n4) return;
    float4 v = ((const float4*)src)[i];
    __nv_bfloat16 h0 = __float2bfloat16(v.x), h1 = __float2bfloat16(v.y);
    __nv_bfloat16 h2 = __float2bfloat16(v.z), h3 = __float2bfloat16(v.w);
    __nv_bfloat16 l0 = __float2bfloat16(v.x - __bfloat162float(h0));
    __nv_bfloat16 l1 = __float2bfloat16(v.y - __bfloat162float(h1));
    __nv_bfloat16 l2 = __float2bfloat16(v.z - __bfloat162float(h2));
    __nv_bfloat16 l3 = __float2bfloat16(v.w - __bfloat162float(h3));
    ((__nv_bfloat162*)hi)[i*2+0] = __nv_bfloat162(h0, h1);
    ((__nv_bfloat162*)hi)[i*2+1] = __nv_bfloat162(h2, h3);
    ((__nv_bfloat162*)lo)[i*2+0] = __nv_bfloat162(l0, l1);
    ((__nv_bfloat162*)lo)[i*2+1] = __nv_bfloat162(l2, l3);
}

// ---------------------------------------------------------------------------
// mma.sync bf16 GEMM, 3-term split. CTA 128x128, K-chunk 64, 8 warps (2Mx4N).
// MODE 0: fp32 C row-major. MODE 1: bf16 hi/lo split scatter to (B,H,L,DK).
// ---------------------------------------------------------------------------
#define TCG_SMEM (4*16384)

template<int MODE>
__global__ void __launch_bounds__(256, 2) mm_gemm(
        const __nv_bfloat16* __restrict__ Ahi, const __nv_bfloat16* __restrict__ Alo,
        const __nv_bfloat16* __restrict__ Bhi, const __nv_bfloat16* __restrict__ Blo,
        const float* __restrict__ bias, float* __restrict__ C,
        __nv_bfloat16* __restrict__ Chi, __nv_bfloat16* __restrict__ Clo,
        int M, int N, int K) {
    extern __shared__ char sm[];
    const uint32_t sbase = smem_to_u32(sm);

    const int tid  = threadIdx.x;
    const int wid  = tid >> 5, lane = tid & 31;
    const int wm   = wid & 1, wn = wid >> 1;
    const int mBase = blockIdx.x * 128, nBase = blockIdx.y * 128;

    float acc[4][4][4] = {};

    const int aRow = (lane & 15);
    const int aKb  = (lane >> 4) * 16;
    const int bRow = ((lane >> 4) & 1) * 8 + (lane & 7);
    const int bKb  = ((lane >> 3) & 1) * 16;

    for (int k0 = 0; k0 < K; k0 += 64) {
        #pragma unroll
        for (int it = 0; it < 16; it++) {
            const int u = it * 256 + tid;
            const int t = u >> 10, idx = u & 1023;
            const int row = idx >> 3, seg = idx & 7;
            const __nv_bfloat16* g;
            if      (t == 0) g = Ahi + (size_t)(mBase + row) * K;
            else if (t == 1) g = Alo + (size_t)(mBase + row) * K;
            else if (t == 2) g = Bhi + (size_t)(nBase + row) * K;
            else             g = Blo + (size_t)(nBase + row) * K;
            float4 v = *(const float4*)(g + k0 + seg * 8);
            const uint32_t sw = SMEM_SWIZZLE_128B(row * 128 + seg * 16);
            *(float4*)(sm + t * 16384 + sw) = v;
        }
        __syncthreads();

        #pragma unroll
        for (int ks = 0; ks < 4; ks++) {
            uint32_t bh[4][2], bl[4][2];
            #pragma unroll
            for (int p = 0; p < 2; p++) {
                const uint32_t boff = SMEM_SWIZZLE_128B(
                    (wn * 32 + p * 16 + bRow) * 128 + ks * 32 + bKb);
                uint32_t r[4];
                ldmx4(r, sbase + 2*16384 + boff);
                bh[p*2+0][0] = r[0]; bh[p*2+0][1] = r[1];
                bh[p*2+1][0] = r[2]; bh[p*2+1][1] = r[3];
                ldmx4(r, sbase + 3*16384 + boff);
                bl[p*2+0][0] = r[0]; bl[p*2+0][1] = r[1];
                bl[p*2+1][0] = r[2]; bl[p*2+1][1] = r[3];
            }
            #pragma unroll
            for (int mf = 0; mf < 4; mf++) {
                const uint32_t aoff = SMEM_SWIZZLE_128B(
                    (wm * 64 + mf * 16 + aRow) * 128 + ks * 32 + aKb);
                uint32_t ah[4], al[4];
                ldmx4(ah, sbase + 0*16384 + aoff);
                ldmx4(al, sbase + 1*16384 + aoff);
                #pragma unroll
                for (int nf = 0; nf < 4; nf++) {
                    mma_bf16(acc[mf][nf], ah, bh[nf]);
                    mma_bf16(acc[mf][nf], ah, bl[nf]);
                    mma_bf16(acc[mf][nf], al, bh[nf]);
                }
            }
        }
        __syncthreads();
    }

    const int rEp = lane >> 2, cEp = (lane & 3) * 2;
    #pragma unroll
    for (int mf = 0; mf < 4; mf++) {
        #pragma unroll
        for (int nf = 0; nf < 4; nf++) {
            const int m0 = mBase + wm * 64 + mf * 16 + rEp;
            const int n  = nBase + wn * 32 + nf * 8 + cEp;
            const float b0 = bias[n], b1 = bias[n + 1];
            float2 v0 = make_float2(acc[mf][nf][0] + b0, acc[mf][nf][1] + b1);
            float2 v1 = make_float2(acc[mf][nf][2] + b0, acc[mf][nf][3] + b1);
            if (MODE == 0) {
                *(float2*)(C + (size_t)m0 * N + n) = v0;
                *(float2*)(C + (size_t)(m0 + 8) * N + n) = v1;
            } else {
                const int h = n >> 6, dk = n & 63;
                const int b_ = m0 / LL, l0 = m0 % LL, l1 = l0 + 8;
                const size_t i0 = (((size_t)b_ * HH + h) * LL + l0) * DKH + dk;
                const size_t i1 = (((size_t)b_ * HH + h) * LL + l1) * DKH + dk;
                __nv_bfloat16 h00 = __float2bfloat16(v0.x), h01 = __float2bfloat16(v0.y);
                __nv_bfloat16 h10 = __float2bfloat16(v1.x), h11 = __float2bfloat16(v1.y);
                *(__nv_bfloat162*)(Chi + i0) = __nv_bfloat162(h00, h01);
                *(__nv_bfloat162*)(Chi + i1) = __nv_bfloat162(h10, h11);
                *(__nv_bfloat162*)(Clo + i0) = __nv_bfloat162(
                    __float2bfloat16(v0.x - __bfloat162float(h00)),
                    __float2bfloat16(v0.y - __bfloat162float(h01)));
                *(__nv_bfloat162*)(Clo + i1) = __nv_bfloat162(
                    __float2bfloat16(v1.x - __bfloat162float(h10)),
                    __float2bfloat16(v1.y - __bfloat162float(h11)));
            }
        }
    }
}

// ---------------------------------------------------------------------------
// Tensor-core causal flash attention. BQ=128, BKV=64, 8 warps (16 rows each).
// S = QK^T and O += P V both via mma.sync bf16 with 3-term splits.
// smem: Qhi[0,16K) Qlo[16K,32K) Khi[32K,40K) Klo[40K,48K) Vhi[48K,56K) Vlo[56K,64K)
// ---------------------------------------------------------------------------
#define ATT_SMEM 65536

__global__ void __launch_bounds__(256) attn_mma(
        const __nv_bfloat16* __restrict__ Qhi, const __nv_bfloat16* __restrict__ Qlo,
        const __nv_bfloat16* __restrict__ Khi, const __nv_bfloat16* __restrict__ Klo,
        const __nv_bfloat16* __restrict__ Vhi, const __nv_bfloat16* __restrict__ Vlo,
        __nv_bfloat16* __restrict__ Ohi, __nv_bfloat16* __restrict__ Olo) {
    extern __shared__ char sm[];
    const uint32_t sb = smem_to_u32(sm);

    const int tid = threadIdx.x, wid = tid >> 5, lane = tid & 31;
    const int qb = blockIdx.x, bh = blockIdx.y;

    // Load Q tile (128 rows x 64 bf16, hi+lo), SW128-swizzled 128B rows
    #pragma unroll
    for (int it = 0; it < 8; it++) {
        const int u = it * 256 + tid;
        const int arr = u >> 10, idx = u & 1023;
        const int row = idx >> 3, seg = idx & 7;
        const __nv_bfloat16* src = arr ? Qlo : Qhi;
        float4 v = *(const float4*)(src + ((size_t)bh * LL + qb * 128 + row) * DKH + seg * 8);
        *(float4*)(sm + arr * 16384 + SMEM_SWIZZLE_128B(row * 128 + seg * 16)) = v;
    }

    float s[8][4];
    float o[8][4] = {};
    float m0 = -1e30f, m1 = -1e30f, l0 = 0.0f, l1 = 0.0f;

    const int r0 = lane >> 2;
    const int ig0 = qb * 128 + wid * 16 + r0, ig1 = ig0 + 8;
    const int aRow = lane & 15;
    const int aKb  = (lane >> 4) * 16;
    const int bRow = ((lane >> 4) & 1) * 8 + (lane & 7);
    const int bKb  = ((lane >> 3) & 1) * 16;
    const int vseg = lane >> 3;
    const int vr   = (vseg & 1) * 8 + (lane & 7);
    const int vcB  = (vseg >> 1) * 16;     // byte offset of n-half within 16n span

    const int kbmax = 2 * qb + 1;
    for (int kb = 0; kb <= kbmax; kb++) {
        // Load K,V hi/lo tiles (64 x 64 bf16 each)
        #pragma unroll
        for (int it = 0; it < 8; it++) {
            const int u = it * 256 + tid;
            const int arr = u >> 9, idx = u & 511;
            const int row = idx >> 3, seg = idx & 7;
            const __nv_bfloat16* src = (arr == 0) ? Khi : (arr == 1) ? Klo
                                     : (arr == 2) ? Vhi : Vlo;
            float4 v = *(const float4*)(src + ((size_t)bh * LL + kb * 64 + row) * DKH + seg * 8);
            *(float4*)(sm + 32768 + arr * 8192 + SMEM_SWIZZLE_128B(row * 128 + seg * 16)) = v;
        }
        __syncthreads();

        // warp's rows all precede this tile's first col? -> fully masked, skip
        const bool skip = (kb * 64 > qb * 128 + wid * 16 + 15);
        if (!skip) {
            // ---- S = Q K^T (3-term split) ----
            #pragma unroll
            for (int nf = 0; nf < 8; nf++)
                s[nf][0] = s[nf][1] = s[nf][2] = s[nf][3] = 0.0f;
            #pragma unroll
            for (int ks = 0; ks < 4; ks++) {
                const uint32_t aoff = SMEM_SWIZZLE_128B((wid * 16 + aRow) * 128 + ks * 32 + aKb);
                uint32_t ah[4], al[4];
                ldmx4(ah, sb + aoff);
                ldmx4(al, sb + 16384 + aoff);
                #pragma unroll
                for (int p = 0; p < 4; p++) {
                    const uint32_t boff = SMEM_SWIZZLE_128B((p * 16 + bRow) * 128 + ks * 32 + bKb);
                    uint32_t rh[4], rl[4];
                    ldmx4(rh, sb + 32768 + boff);
                    ldmx4(rl, sb + 40960 + boff);
                    mma_bf16(s[2*p],   ah, rh);
                    mma_bf16(s[2*p],   ah, rl);
                    mma_bf16(s[2*p],   al, rh);
                    mma_bf16(s[2*p+1], ah, rh + 2);
                    mma_bf16(s[2*p+1], ah, rl + 2);
                    mma_bf16(s[2*p+1], al, rh + 2);
                }
            }

            // ---- online softmax (rows live in one warp; quad shuffles) ----
            const bool needMask = (kb >= 2 * qb);
            float mx0 = -1e30f, mx1 = -1e30f;
            #pragma unroll
            for (int nf = 0; nf < 8; nf++) {
                #pragma unroll
                for (int c = 0; c < 4; c++) {
                    float v = s[nf][c] * 0.125f;
                    if (needMask) {
                        const int jg = kb * 64 + nf * 8 + 2 * (lane & 3) + (c & 1);
                        if (jg > ((c < 2) ? ig0 : ig1)) v = -1e30f;
                    }
                    s[nf][c] = v;
                }
                mx0 = fmaxf(mx0, fmaxf(s[nf][0], s[nf][1]));
                mx1 = fmaxf(mx1, fmaxf(s[nf][2], s[nf][3]));
            }
            mx0 = fmaxf(mx0, __shfl_xor_sync(~0u, mx0, 1));
            mx0 = fmaxf(mx0, __shfl_xor_sync(~0u, mx0, 2));
            mx1 = fmaxf(mx1, __shfl_xor_sync(~0u, mx1, 1));
            mx1 = fmaxf(mx1, __shfl_xor_sync(~0u, mx1, 2));
            const float mn0 = fmaxf(m0, mx0), mn1 = fmaxf(m1, mx1);
            const float al0 = __expf(m0 - mn0), al1 = __expf(m1 - mn1);
            m0 = mn0; m1 = mn1;
            float rs0 = 0.0f, rs1 = 0.0f;
            #pragma unroll
            for (int nf = 0; nf < 8; nf++) {
                s[nf][0] = __expf(s[nf][0] - mn0);
                s[nf][1] = __expf(s[nf][1] - mn0);
                s[nf][2] = __expf(s[nf][2] - mn1);
                s[nf][3] = __expf(s[nf][3] - mn1);
                rs0 += s[nf][0] + s[nf][1];
                rs1 += s[nf][2] + s[nf][3];
            }
            rs0 += __shfl_xor_sync(~0u, rs0, 1);
            rs0 += __shfl_xor_sync(~0u, rs0, 2);
            rs1 += __shfl_xor_sync(~0u, rs1, 1);
            rs1 += __shfl_xor_sync(~0u, rs1, 2);
            l0 = l0 * al0 + rs0;
            l1 = l1 * al1 + rs1;
            #pragma unroll
            for (int nf = 0; nf < 8; nf++) {
                o[nf][0] *= al0; o[nf][1] *= al0;
                o[nf][2] *= al1; o[nf][3] *= al1;
            }

            // ---- O += P V (3-term split; P from S frags, V via trans ldmatrix) ----
            #pragma unroll
            for (int ks = 0; ks < 4; ks++) {
                uint32_t aph[4], apl[4];
                #pragma unroll
                for (int half = 0; half < 2; half++) {   // a0/a1 from nf=2ks, a2/a3 from 2ks+1
                    const int nf = 2 * ks + half;
                    __nv_bfloat16 hA = __float2bfloat16(s[nf][0]);
                    __nv_bfloat16 hB = __float2bfloat16(s[nf][1]);
                    __nv_bfloat16 hC = __float2bfloat16(s[nf][2]);
                    __nv_bfloat16 hD = __float2bfloat16(s[nf][3]);
                    aph[half*2+0] = pack_bf16(hA, hB);
                    aph[half*2+1] = pack_bf16(hC, hD);
                    apl[half*2+0] = pack_bf16(
                        __float2bfloat16(s[nf][0] - __bfloat162float(hA)),
                        __float2bfloat16(s[nf][1] - __bfloat162float(hB)));
                    apl[half*2+1] = pack_bf16(
                        __float2bfloat16(s[nf][2] - __bfloat162float(hC)),
                        __float2bfloat16(s[nf][3] - __bfloat162float(hD)));
                }
                #pragma unroll
                for (int q = 0; q < 4; q++) {
                    const uint32_t voff = SMEM_SWIZZLE_128B((ks * 16 + vr) * 128 + q * 32 + vcB);
                    uint32_t vh[4], vl[4];
                    ldmx4t(vh, sb + 49152 + voff);
                    ldmx4t(vl, sb + 57344 + voff);
                    mma_bf16(o[2*q],   aph, vh);
                    mma_bf16(o[2*q],   aph, vl);
                    mma_bf16(o[2*q],   apl, vh);
                    mma_bf16(o[2*q+1], aph, vh + 2);
                    mma_bf16(o[2*q+1], aph, vl + 2);
                    mma_bf16(o[2*q+1], apl, vh + 2);
                }
            }
        }
        __syncthreads();
    }

    // Epilogue: normalize, split hi/lo, scatter to (B, L, D)
    const int b = bh >> 4, h = bh & 15;
    const float inv0 = 1.0f / l0, inv1 = 1.0f / l1;
    const int lg0 = qb * 128 + wid * 16 + r0, lg1 = lg0 + 8;
    #pragma unroll
    for (int nf = 0; nf < 8; nf++) {
        const int d = h * 64 + nf * 8 + 2 * (lane & 3);
        const size_t i0 = ((size_t)b * LL + lg0) * DD + d;
        const size_t i1 = ((size_t)b * LL + lg1) * DD + d;
        float a0 = o[nf][0] * inv0, a1 = o[nf][1] * inv0;
        float b0_ = o[nf][2] * inv1, b1_ = o[nf][3] * inv1;
        __nv_bfloat16 h00 = __float2bfloat16(a0), h01 = __float2bfloat16(a1);
        __nv_bfloat16 h10 = __float2bfloat16(b0_), h11 = __float2bfloat16(b1_);
        *(__nv_bfloat162*)(Ohi + i0) = __nv_bfloat162(h00, h01);
        *(__nv_bfloat162*)(Ohi + i1) = __nv_bfloat162(h10, h11);
        *(__nv_bfloat162*)(Olo + i0) = __nv_bfloat162(
            __float2bfloat16(a0 - __bfloat162float(h00)),
            __float2bfloat16(a1 - __bfloat162float(h01)));
        *(__nv_bfloat162*)(Olo + i1) = __nv_bfloat162(
            __float2bfloat16(b0_ - __bfloat162float(h10)),
            __float2bfloat16(b1_ - __bfloat162float(h11)));
    }
}

// ---------------------------------------------------------------------------
extern "C" void kernel_launch(void* const* d_in, const int* in_sizes, int n_in,
                              void* d_out, int out_size) {
    (void)in_sizes; (void)n_in; (void)out_size;
    const float* x  = (const float*)d_in[0];
    const float* wq = (const float*)d_in[1];
    const float* bq = (const float*)d_in[2];
    const float* wk = (const float*)d_in[3];
    const float* bk = (const float*)d_in[4];
    const float* wv = (const float*)d_in[5];
    const float* bv = (const float*)d_in[6];
    const float* wo = (const float*)d_in[7];
    const float* bo = (const float*)d_in[8];

    __nv_bfloat16 *xhi, *xlo, *whi, *wlo;
    __nv_bfloat16 *qhi, *qlo, *khi, *klo, *vhi, *vlo, *ohi, *olo;
    cudaGetSymbolAddress((void**)&xhi, g_xhi);
    cudaGetSymbolAddress((void**)&xlo, g_xlo);
    cudaGetSymbolAddress((void**)&whi, g_whi);
    cudaGetSymbolAddress((void**)&wlo, g_wlo);
    cudaGetSymbolAddress((void**)&qhi, g_qhi);
    cudaGetSymbolAddress((void**)&qlo, g_qlo);
    cudaGetSymbolAddress((void**)&khi, g_khi);
    cudaGetSymbolAddress((void**)&klo, g_klo);
    cudaGetSymbolAddress((void**)&vhi, g_vhi);
    cudaGetSymbolAddress((void**)&vlo, g_vlo);
    cudaGetSymbolAddress((void**)&ohi, g_ohi);
    cudaGetSymbolAddress((void**)&olo, g_olo);

    const int nx4 = MTOT * DD / 4;
    const int nw4 = DD * DD / 4;
    split_kernel<<<nx4 / 256, 256>>>(x, xhi, xlo, nx4);
    split_kernel<<<nw4 / 256, 256>>>(wq, whi + 0*DD*DD, wlo + 0*DD*DD, nw4);
    split_kernel<<<nw4 / 256, 256>>>(wk, whi + 1*DD*DD, wlo + 1*DD*DD, nw4);
    split_kernel<<<nw4 / 256, 256>>>(wv, whi + 2*DD*DD, wlo + 2*DD*DD, nw4);
    split_kernel<<<nw4 / 256, 256>>>(wo, whi + 3*DD*DD, wlo + 3*DD*DD, nw4);

    cudaFuncSetAttribute(mm_gemm<0>, cudaFuncAttributeMaxDynamicSharedMemorySize, TCG_SMEM);
    cudaFuncSetAttribute(mm_gemm<1>, cudaFuncAttributeMaxDynamicSharedMemorySize, TCG_SMEM);
    cudaFuncSetAttribute(attn_mma, cudaFuncAttributeMaxDynamicSharedMemorySize, ATT_SMEM);

    dim3 gp(MTOT / 128, DD / 128);   // 32 x 8

    mm_gemm<1><<<gp, 256, TCG_SMEM>>>(xhi, xlo, whi + 0*DD*DD, wlo + 0*DD*DD, bq,
                                      nullptr, qhi, qlo, MTOT, DD, DD);
    mm_gemm<1><<<gp, 256, TCG_SMEM>>>(xhi, xlo, whi + 1*DD*DD, wlo + 1*DD*DD, bk,
                                      nullptr, khi, klo, MTOT, DD, DD);
    mm_gemm<1><<<gp, 256, TCG_SMEM>>>(xhi, xlo, whi + 2*DD*DD, wlo + 2*DD*DD, bv,
                                      nullptr, vhi, vlo, MTOT, DD, DD);

    attn_mma<<<dim3(LL / 128, BB * HH), 256, ATT_SMEM>>>(qhi, qlo, khi, klo,
                                                         vhi, vlo, ohi, olo);

    mm_gemm<0><<<gp, 256, TCG_SMEM>>>(ohi, olo, whi + 3*DD*DD, wlo + 3*DD*DD, bo,
                                      (float*)d_out, nullptr, nullptr, MTOT, DD, DD);
}

// round 6
// speedup vs baseline: 3.4826x; 1.0934x over previous
#include <cuda_runtime.h>
#include <cuda_bf16.h>
#include <cstdint>

// Problem constants
#define BB 2
#define LL 2048
#define DD 1024
#define HH 16
#define DKH 64
#define MTOT (BB*LL)   // 4096

// ---------------------------------------------------------------------------
// Scratch (no cudaMalloc allowed) — all bf16 hi/lo split pairs
// ---------------------------------------------------------------------------
__device__ __nv_bfloat16 g_xhi[MTOT*DD], g_xlo[MTOT*DD];
__device__ __nv_bfloat16 g_whi[4*DD*DD], g_wlo[4*DD*DD];
__device__ __nv_bfloat16 g_qhi[BB*HH*LL*DKH], g_qlo[BB*HH*LL*DKH];
__device__ __nv_bfloat16 g_khi[BB*HH*LL*DKH], g_klo[BB*HH*LL*DKH];
__device__ __nv_bfloat16 g_vhi[BB*HH*LL*DKH], g_vlo[BB*HH*LL*DKH];
__device__ __nv_bfloat16 g_ohi[MTOT*DD], g_olo[MTOT*DD];

__device__ __forceinline__ uint32_t smem_to_u32(const void* p) {
    uint32_t a;
    asm("{ .reg .u64 t; cvta.to.shared.u64 t, %1; cvt.u32.u64 %0, t; }" : "=r"(a) : "l"(p));
    return a;
}
#define SMEM_SWIZZLE_128B(o) ((o) ^ (((o) >> 3) & 0x70))

#define CP_ASYNC16(dst_u32, gptr) \
    asm volatile("cp.async.cg.shared.global [%0], [%1], 16;" \
                 :: "r"(dst_u32), "l"(gptr) : "memory")
#define CP_COMMIT() asm volatile("cp.async.commit_group;" ::: "memory")
#define CP_WAIT0()  asm volatile("cp.async.wait_group 0;" ::: "memory")

__device__ __forceinline__ void ldmx4(uint32_t* r, uint32_t addr) {
    asm volatile("ldmatrix.sync.aligned.m8n8.x4.shared.b16 {%0,%1,%2,%3}, [%4];"
                 : "=r"(r[0]), "=r"(r[1]), "=r"(r[2]), "=r"(r[3]) : "r"(addr));
}
__device__ __forceinline__ void ldmx4t(uint32_t* r, uint32_t addr) {
    asm volatile("ldmatrix.sync.aligned.m8n8.x4.trans.shared.b16 {%0,%1,%2,%3}, [%4];"
                 : "=r"(r[0]), "=r"(r[1]), "=r"(r[2]), "=r"(r[3]) : "r"(addr));
}
__device__ __forceinline__ void mma_bf16(float* c, const uint32_t* a, const uint32_t* b) {
    asm volatile("mma.sync.aligned.m16n8k16.row.col.f32.bf16.bf16.f32 "
                 "{%0,%1,%2,%3}, {%4,%5,%6,%7}, {%8,%9}, {%0,%1,%2,%3};"
                 : "+f"(c[0]), "+f"(c[1]), "+f"(c[2]), "+f"(c[3])
                 : "r"(a[0]), "r"(a[1]), "r"(a[2]), "r"(a[3]), "r"(b[0]), "r"(b[1]));
}
__device__ __forceinline__ uint32_t pack_bf16(__nv_bfloat16 x, __nv_bfloat16 y) {
    __nv_bfloat162 h; h.x = x; h.y = y;
    uint32_t u; __builtin_memcpy(&u, &h, 4);
    return u;
}

// ---------------------------------------------------------------------------
// Fused fp32 -> bf16 hi/lo split for x + 4 weights (one launch)
// ---------------------------------------------------------------------------
__global__ void split_all(const float* __restrict__ x,
                          const float* __restrict__ wq, const float* __restrict__ wk,
                          const float* __restrict__ wv, const float* __restrict__ wo,
                          __nv_bfloat16* __restrict__ xhi, __nv_bfloat16* __restrict__ xlo,
                          __nv_bfloat16* __restrict__ whi, __nv_bfloat16* __restrict__ wlo) {
    const int bid = blockIdx.x;
    const float* src;
    __nv_bfloat16 *hi, *lo;
    int i;
    if (bid < 4096) {
        src = x; hi = xhi; lo = xlo;
        i = bid * 256 + threadIdx.x;
    } else {
        const int wsel = (bid - 4096) >> 10;
        const int lb   = (bid - 4096) & 1023;
        src = (wsel == 0) ? wq : (wsel == 1) ? wk : (wsel == 2) ? wv : wo;
        hi = whi + (size_t)wsel * DD * DD;
        lo = wlo + (size_t)wsel * DD * DD;
        i = lb * 256 + threadIdx.x;
    }
    float4 v = ((const float4*)src)[i];
    __nv_bfloat16 h0 = __float2bfloat16(v.x), h1 = __float2bfloat16(v.y);
    __nv_bfloat16 h2 = __float2bfloat16(v.z), h3 = __float2bfloat16(v.w);
    ((__nv_bfloat162*)hi)[i*2+0] = __nv_bfloat162(h0, h1);
    ((__nv_bfloat162*)hi)[i*2+1] = __nv_bfloat162(h2, h3);
    ((__nv_bfloat162*)lo)[i*2+0] = __nv_bfloat162(
        __float2bfloat16(v.x - __bfloat162float(h0)),
        __float2bfloat16(v.y - __bfloat162float(h1)));
    ((__nv_bfloat162*)lo)[i*2+1] = __nv_bfloat162(
        __float2bfloat16(v.z - __bfloat162float(h2)),
        __float2bfloat16(v.w - __bfloat162float(h3)));
}

// ---------------------------------------------------------------------------
// mma.sync bf16 GEMM, 3-term split, cp.async 2-stage pipeline.
// CTA 128x128, K-chunk 64, 8 warps (2Mx4N).
// MODE 0: fp32 C row-major. MODE 1: bf16 hi/lo split scatter to (B,H,L,DK).
// smem per stage (64KB): Ahi@0 Alo@16K Bhi@32K Blo@48K; 2 stages = 128KB.
// ---------------------------------------------------------------------------
#define TCG_SMEM (2*65536)

template<int MODE>
__global__ void __launch_bounds__(256) mm_gemm(
        const __nv_bfloat16* __restrict__ Ahi, const __nv_bfloat16* __restrict__ Alo,
        const __nv_bfloat16* __restrict__ Bhi, const __nv_bfloat16* __restrict__ Blo,
        const float* __restrict__ bias, float* __restrict__ C,
        __nv_bfloat16* __restrict__ Chi, __nv_bfloat16* __restrict__ Clo,
        int M, int N, int K) {
    extern __shared__ char sm[];
    const uint32_t sbase = smem_to_u32(sm);

    const int tid  = threadIdx.x;
    const int wid  = tid >> 5, lane = tid & 31;
    const int wm   = wid & 1, wn = wid >> 1;
    const int mBase = blockIdx.x * 128, nBase = blockIdx.y * 128;

    float acc[4][4][4] = {};

    const int aRow = (lane & 15);
    const int aKb  = (lane >> 4) * 16;
    const int bRow = ((lane >> 4) & 1) * 8 + (lane & 7);
    const int bKb  = ((lane >> 3) & 1) * 16;

    auto issue_chunk = [&](int k0, int st) {
        #pragma unroll
        for (int it = 0; it < 16; it++) {
            const int u = it * 256 + tid;
            const int t = u >> 10, idx = u & 1023;
            const int row = idx >> 3, seg = idx & 7;
            const __nv_bfloat16* g;
            if      (t == 0) g = Ahi + (size_t)(mBase + row) * K;
            else if (t == 1) g = Alo + (size_t)(mBase + row) * K;
            else if (t == 2) g = Bhi + (size_t)(nBase + row) * K;
            else             g = Blo + (size_t)(nBase + row) * K;
            const uint32_t d = sbase + st * 65536 + t * 16384
                             + SMEM_SWIZZLE_128B(row * 128 + seg * 16);
            CP_ASYNC16(d, g + k0 + seg * 8);
        }
    };

    issue_chunk(0, 0);
    CP_COMMIT();

    const int nChunks = K / 64;
    for (int c = 0; c < nChunks; c++) {
        CP_WAIT0();
        __syncthreads();
        if (c + 1 < nChunks) {
            issue_chunk((c + 1) * 64, (c + 1) & 1);
            CP_COMMIT();
        }
        const uint32_t sb0 = sbase + (c & 1) * 65536;

        #pragma unroll
        for (int ks = 0; ks < 4; ks++) {
            uint32_t bh[4][2], bl[4][2];
            #pragma unroll
            for (int p = 0; p < 2; p++) {
                const uint32_t boff = SMEM_SWIZZLE_128B(
                    (wn * 32 + p * 16 + bRow) * 128 + ks * 32 + bKb);
                uint32_t r[4];
                ldmx4(r, sb0 + 32768 + boff);
                bh[p*2+0][0] = r[0]; bh[p*2+0][1] = r[1];
                bh[p*2+1][0] = r[2]; bh[p*2+1][1] = r[3];
                ldmx4(r, sb0 + 49152 + boff);
                bl[p*2+0][0] = r[0]; bl[p*2+0][1] = r[1];
                bl[p*2+1][0] = r[2]; bl[p*2+1][1] = r[3];
            }
            #pragma unroll
            for (int mf = 0; mf < 4; mf++) {
                const uint32_t aoff = SMEM_SWIZZLE_128B(
                    (wm * 64 + mf * 16 + aRow) * 128 + ks * 32 + aKb);
                uint32_t ah[4], al[4];
                ldmx4(ah, sb0 + aoff);
                ldmx4(al, sb0 + 16384 + aoff);
                #pragma unroll
                for (int nf = 0; nf < 4; nf++) {
                    mma_bf16(acc[mf][nf], ah, bh[nf]);
                    mma_bf16(acc[mf][nf], ah, bl[nf]);
                    mma_bf16(acc[mf][nf], al, bh[nf]);
                }
            }
        }
    }

    const int rEp = lane >> 2, cEp = (lane & 3) * 2;
    #pragma unroll
    for (int mf = 0; mf < 4; mf++) {
        #pragma unroll
        for (int nf = 0; nf < 4; nf++) {
            const int m0 = mBase + wm * 64 + mf * 16 + rEp;
            const int n  = nBase + wn * 32 + nf * 8 + cEp;
            const float b0 = bias[n], b1 = bias[n + 1];
            float2 v0 = make_float2(acc[mf][nf][0] + b0, acc[mf][nf][1] + b1);
            float2 v1 = make_float2(acc[mf][nf][2] + b0, acc[mf][nf][3] + b1);
            if (MODE == 0) {
                *(float2*)(C + (size_t)m0 * N + n) = v0;
                *(float2*)(C + (size_t)(m0 + 8) * N + n) = v1;
            } else {
                const int h = n >> 6, dk = n & 63;
                const int b_ = m0 / LL, l0 = m0 % LL, l1 = l0 + 8;
                const size_t i0 = (((size_t)b_ * HH + h) * LL + l0) * DKH + dk;
                const size_t i1 = (((size_t)b_ * HH + h) * LL + l1) * DKH + dk;
                __nv_bfloat16 h00 = __float2bfloat16(v0.x), h01 = __float2bfloat16(v0.y);
                __nv_bfloat16 h10 = __float2bfloat16(v1.x), h11 = __float2bfloat16(v1.y);
                *(__nv_bfloat162*)(Chi + i0) = __nv_bfloat162(h00, h01);
                *(__nv_bfloat162*)(Chi + i1) = __nv_bfloat162(h10, h11);
                *(__nv_bfloat162*)(Clo + i0) = __nv_bfloat162(
                    __float2bfloat16(v0.x - __bfloat162float(h00)),
                    __float2bfloat16(v0.y - __bfloat162float(h01)));
                *(__nv_bfloat162*)(Clo + i1) = __nv_bfloat162(
                    __float2bfloat16(v1.x - __bfloat162float(h10)),
                    __float2bfloat16(v1.y - __bfloat162float(h11)));
            }
        }
    }
}

// ---------------------------------------------------------------------------
// Tensor-core causal flash attention, cp.async 2-stage K/V pipeline.
// BQ=128, BKV=64, 8 warps (16 rows each).
// smem: Qhi@0 Qlo@16K; stage s at 32K+s*32K: Khi@+0 Klo@+8K Vhi@+16K Vlo@+24K
// ---------------------------------------------------------------------------
#define ATT_SMEM (32768 + 2*32768)

__global__ void __launch_bounds__(256, 2) attn_mma(
        const __nv_bfloat16* __restrict__ Qhi, const __nv_bfloat16* __restrict__ Qlo,
        const __nv_bfloat16* __restrict__ Khi, const __nv_bfloat16* __restrict__ Klo,
        const __nv_bfloat16* __restrict__ Vhi, const __nv_bfloat16* __restrict__ Vlo,
        __nv_bfloat16* __restrict__ Ohi, __nv_bfloat16* __restrict__ Olo) {
    extern __shared__ char sm[];
    const uint32_t sb = smem_to_u32(sm);

    const int tid = threadIdx.x, wid = tid >> 5, lane = tid & 31;
    const int qb = blockIdx.x, bh = blockIdx.y;

    auto issue_kv = [&](int kb, int st) {
        #pragma unroll
        for (int it = 0; it < 8; it++) {
            const int u = it * 256 + tid;
            const int arr = u >> 9, idx = u & 511;
            const int row = idx >> 3, seg = idx & 7;
            const __nv_bfloat16* src = (arr == 0) ? Khi : (arr == 1) ? Klo
                                     : (arr == 2) ? Vhi : Vlo;
            const uint32_t d = sb + 32768 + st * 32768 + arr * 8192
                             + SMEM_SWIZZLE_128B(row * 128 + seg * 16);
            CP_ASYNC16(d, src + ((size_t)bh * LL + kb * 64 + row) * DKH + seg * 8);
        }
    };

    // Q (hi+lo) via cp.async into [0, 32K)
    #pragma unroll
    for (int it = 0; it < 8; it++) {
        const int u = it * 256 + tid;
        const int arr = u >> 10, idx = u & 1023;
        const int row = idx >> 3, seg = idx & 7;
        const __nv_bfloat16* src = arr ? Qlo : Qhi;
        const uint32_t d = sb + arr * 16384 + SMEM_SWIZZLE_128B(row * 128 + seg * 16);
        CP_ASYNC16(d, src + ((size_t)bh * LL + qb * 128 + row) * DKH + seg * 8);
    }
    issue_kv(0, 0);
    CP_COMMIT();

    float s[8][4];
    float o[8][4] = {};
    float m0 = -1e30f, m1 = -1e30f, l0 = 0.0f, l1 = 0.0f;

    const int r0 = lane >> 2;
    const int ig0 = qb * 128 + wid * 16 + r0, ig1 = ig0 + 8;
    const int aRow = lane & 15;
    const int aKb  = (lane >> 4) * 16;
    const int bRow = ((lane >> 4) & 1) * 8 + (lane & 7);
    const int bKb  = ((lane >> 3) & 1) * 16;
    const int vseg = lane >> 3;
    const int vr   = (vseg & 1) * 8 + (lane & 7);
    const int vcB  = (vseg >> 1) * 16;

    const int kbmax = 2 * qb + 1;
    for (int kb = 0; kb <= kbmax; kb++) {
        CP_WAIT0();
        __syncthreads();
        if (kb < kbmax) {
            issue_kv(kb + 1, (kb + 1) & 1);
            CP_COMMIT();
        }

        const bool skip = (kb * 64 > qb * 128 + wid * 16 + 15);
        if (!skip) {
            const uint32_t kvb = sb + 32768 + (kb & 1) * 32768;

            // ---- S = Q K^T (3-term split) ----
            #pragma unroll
            for (int nf = 0; nf < 8; nf++)
                s[nf][0] = s[nf][1] = s[nf][2] = s[nf][3] = 0.0f;
            #pragma unroll
            for (int ks = 0; ks < 4; ks++) {
                const uint32_t aoff = SMEM_SWIZZLE_128B((wid * 16 + aRow) * 128 + ks * 32 + aKb);
                uint32_t ah[4], al[4];
                ldmx4(ah, sb + aoff);
                ldmx4(al, sb + 16384 + aoff);
                #pragma unroll
                for (int p = 0; p < 4; p++) {
                    const uint32_t boff = SMEM_SWIZZLE_128B((p * 16 + bRow) * 128 + ks * 32 + bKb);
                    uint32_t rh[4], rl[4];
                    ldmx4(rh, kvb + boff);
                    ldmx4(rl, kvb + 8192 + boff);
                    mma_bf16(s[2*p],   ah, rh);
                    mma_bf16(s[2*p],   ah, rl);
                    mma_bf16(s[2*p],   al, rh);
                    mma_bf16(s[2*p+1], ah, rh + 2);
                    mma_bf16(s[2*p+1], ah, rl + 2);
                    mma_bf16(s[2*p+1], al, rh + 2);
                }
            }

            // ---- online softmax (quad shuffles) ----
            const bool needMask = (kb >= 2 * qb);
            float mx0 = -1e30f, mx1 = -1e30f;
            #pragma unroll
            for (int nf = 0; nf < 8; nf++) {
                #pragma unroll
                for (int c = 0; c < 4; c++) {
                    float v = s[nf][c] * 0.125f;
                    if (needMask) {
                        const int jg = kb * 64 + nf * 8 + 2 * (lane & 3) + (c & 1);
                        if (jg > ((c < 2) ? ig0 : ig1)) v = -1e30f;
                    }
                    s[nf][c] = v;
                }
                mx0 = fmaxf(mx0, fmaxf(s[nf][0], s[nf][1]));
                mx1 = fmaxf(mx1, fmaxf(s[nf][2], s[nf][3]));
            }
            mx0 = fmaxf(mx0, __shfl_xor_sync(~0u, mx0, 1));
            mx0 = fmaxf(mx0, __shfl_xor_sync(~0u, mx0, 2));
            mx1 = fmaxf(mx1, __shfl_xor_sync(~0u, mx1, 1));
            mx1 = fmaxf(mx1, __shfl_xor_sync(~0u, mx1, 2));
            const float mn0 = fmaxf(m0, mx0), mn1 = fmaxf(m1, mx1);
            const float al0 = __expf(m0 - mn0), al1 = __expf(m1 - mn1);
            m0 = mn0; m1 = mn1;
            float rs0 = 0.0f, rs1 = 0.0f;
            #pragma unroll
            for (int nf = 0; nf < 8; nf++) {
                s[nf][0] = __expf(s[nf][0] - mn0);
                s[nf][1] = __expf(s[nf][1] - mn0);
                s[nf][2] = __expf(s[nf][2] - mn1);
                s[nf][3] = __expf(s[nf][3] - mn1);
                rs0 += s[nf][0] + s[nf][1];
                rs1 += s[nf][2] + s[nf][3];
            }
            rs0 += __shfl_xor_sync(~0u, rs0, 1);
            rs0 += __shfl_xor_sync(~0u, rs0, 2);
            rs1 += __shfl_xor_sync(~0u, rs1, 1);
            rs1 += __shfl_xor_sync(~0u, rs1, 2);
            l0 = l0 * al0 + rs0;
            l1 = l1 * al1 + rs1;
            #pragma unroll
            for (int nf = 0; nf < 8; nf++) {
                o[nf][0] *= al0; o[nf][1] *= al0;
                o[nf][2] *= al1; o[nf][3] *= al1;
            }

            // ---- O += P V (3-term split) ----
            #pragma unroll
            for (int ks = 0; ks < 4; ks++) {
                uint32_t aph[4], apl[4];
                #pragma unroll
                for (int half = 0; half < 2; half++) {
                    const int nf = 2 * ks + half;
                    __nv_bfloat16 hA = __float2bfloat16(s[nf][0]);
                    __nv_bfloat16 hB = __float2bfloat16(s[nf][1]);
                    __nv_bfloat16 hC = __float2bfloat16(s[nf][2]);
                    __nv_bfloat16 hD = __float2bfloat16(s[nf][3]);
                    aph[half*2+0] = pack_bf16(hA, hB);
                    aph[half*2+1] = pack_bf16(hC, hD);
                    apl[half*2+0] = pack_bf16(
                        __float2bfloat16(s[nf][0] - __bfloat162float(hA)),
                        __float2bfloat16(s[nf][1] - __bfloat162float(hB)));
                    apl[half*2+1] = pack_bf16(
                        __float2bfloat16(s[nf][2] - __bfloat162float(hC)),
                        __float2bfloat16(s[nf][3] - __bfloat162float(hD)));
                }
                #pragma unroll
                for (int q = 0; q < 4; q++) {
                    const uint32_t voff = SMEM_SWIZZLE_128B((ks * 16 + vr) * 128 + q * 32 + vcB);
                    uint32_t vh[4], vl[4];
                    ldmx4t(vh, kvb + 16384 + voff);
                    ldmx4t(vl, kvb + 24576 + voff);
                    mma_bf16(o[2*q],   aph, vh);
                    mma_bf16(o[2*q],   aph, vl);
                    mma_bf16(o[2*q],   apl, vh);
                    mma_bf16(o[2*q+1], aph, vh + 2);
                    mma_bf16(o[2*q+1], aph, vl + 2);
                    mma_bf16(o[2*q+1], apl, vh + 2);
                }
            }
        }
    }

    // Epilogue: normalize, split hi/lo, scatter to (B, L, D)
    const int b = bh >> 4, h = bh & 15;
    const float inv0 = 1.0f / l0, inv1 = 1.0f / l1;
    const int lg0 = qb * 128 + wid * 16 + r0, lg1 = lg0 + 8;
    #pragma unroll
    for (int nf = 0; nf < 8; nf++) {
        const int d = h * 64 + nf * 8 + 2 * (lane & 3);
        const size_t i0 = ((size_t)b * LL + lg0) * DD + d;
        const size_t i1 = ((size_t)b * LL + lg1) * DD + d;
        float a0 = o[nf][0] * inv0, a1 = o[nf][1] * inv0;
        float b0_ = o[nf][2] * inv1, b1_ = o[nf][3] * inv1;
        __nv_bfloat16 h00 = __float2bfloat16(a0), h01 = __float2bfloat16(a1);
        __nv_bfloat16 h10 = __float2bfloat16(b0_), h11 = __float2bfloat16(b1_);
        *(__nv_bfloat162*)(Ohi + i0) = __nv_bfloat162(h00, h01);
        *(__nv_bfloat162*)(Ohi + i1) = __nv_bfloat162(h10, h11);
        *(__nv_bfloat162*)(Olo + i0) = __nv_bfloat162(
            __float2bfloat16(a0 - __bfloat162float(h00)),
            __float2bfloat16(a1 - __bfloat162float(h01)));
        *(__nv_bfloat162*)(Olo + i1) = __nv_bfloat162(
            __float2bfloat16(b0_ - __bfloat162float(h10)),
            __float2bfloat16(b1_ - __bfloat162float(h11)));
    }
}

// ---------------------------------------------------------------------------
extern "C" void kernel_launch(void* const* d_in, const int* in_sizes, int n_in,
                              void* d_out, int out_size) {
    (void)in_sizes; (void)n_in; (void)out_size;
    const float* x  = (const float*)d_in[0];
    const float* wq = (const float*)d_in[1];
    const float* bq = (const float*)d_in[2];
    const float* wk = (const float*)d_in[3];
    const float* bk = (const float*)d_in[4];
    const float* wv = (const float*)d_in[5];
    const float* bv = (const float*)d_in[6];
    const float* wo = (const float*)d_in[7];
    const float* bo = (const float*)d_in[8];

    __nv_bfloat16 *xhi, *xlo, *whi, *wlo;
    __nv_bfloat16 *qhi, *qlo, *khi, *klo, *vhi, *vlo, *ohi, *olo;
    cudaGetSymbolAddress((void**)&xhi, g_xhi);
    cudaGetSymbolAddress((void**)&xlo, g_xlo);
    cudaGetSymbolAddress((void**)&whi, g_whi);
    cudaGetSymbolAddress((void**)&wlo, g_wlo);
    cudaGetSymbolAddress((void**)&qhi, g_qhi);
    cudaGetSymbolAddress((void**)&qlo, g_qlo);
    cudaGetSymbolAddress((void**)&khi, g_khi);
    cudaGetSymbolAddress((void**)&klo, g_klo);
    cudaGetSymbolAddress((void**)&vhi, g_vhi);
    cudaGetSymbolAddress((void**)&vlo, g_vlo);
    cudaGetSymbolAddress((void**)&ohi, g_ohi);
    cudaGetSymbolAddress((void**)&olo, g_olo);

    split_all<<<8192, 256>>>(x, wq, wk, wv, wo, xhi, xlo, whi, wlo);

    cudaFuncSetAttribute(mm_gemm<0>, cudaFuncAttributeMaxDynamicSharedMemorySize, TCG_SMEM);
    cudaFuncSetAttribute(mm_gemm<1>, cudaFuncAttributeMaxDynamicSharedMemorySize, TCG_SMEM);
    cudaFuncSetAttribute(attn_mma, cudaFuncAttributeMaxDynamicSharedMemorySize, ATT_SMEM);

    dim3 gp(MTOT / 128, DD / 128);   // 32 x 8

    mm_gemm<1><<<gp, 256, TCG_SMEM>>>(xhi, xlo, whi + 0*DD*DD, wlo + 0*DD*DD, bq,
                                      nullptr, qhi, qlo, MTOT, DD, DD);
    mm_gemm<1><<<gp, 256, TCG_SMEM>>>(xhi, xlo, whi + 1*DD*DD, wlo + 1*DD*DD, bk,
                                      nullptr, khi, klo, MTOT, DD, DD);
    mm_gemm<1><<<gp, 256, TCG_SMEM>>>(xhi, xlo, whi + 2*DD*DD, wlo + 2*DD*DD, bv,
                                      nullptr, vhi, vlo, MTOT, DD, DD);

    attn_mma<<<dim3(LL / 128, BB * HH), 256, ATT_SMEM>>>(qhi, qlo, khi, klo,
                                                         vhi, vlo, ohi, olo);

    mm_gemm<0><<<gp, 256, TCG_SMEM>>>(ohi, olo, whi + 3*DD*DD, wlo + 3*DD*DD, bo,
                                      (float*)d_out, nullptr, nullptr, MTOT, DD, DD);
}